// round 3
// baseline (speedup 1.0000x reference)
#include <cuda_runtime.h>
#include <cuda_bf16.h>

// Sampler_32865089749571: temperature + top-p/top-k + softmax + argmax reduces
// to row-wise argmax of the raw logits (rank-0 of the sort is never masked;
// temperature and softmax are monotone; tie-break = lowest index, matched here).
//
// R3: load-balanced split — 4 chunks/row -> 1024 CTAs (1024/148 = 6.92, ~1.2%
// per-SM imbalance vs ~2x for 256 CTAs), partials combined by a tiny 2nd kernel.

#define VOCAB   128000
#define BATCH   256
#define ROW4    (VOCAB / 4)    // 32000 float4 per row
#define SPLIT   4
#define CHUNK4  (ROW4 / SPLIT) // 8000 float4 per chunk
#define NT      256
#define NWARP   (NT / 32)

// Partial results: packed (orderable_key << 32) | ~idx per (row, chunk).
// Fully overwritten every launch -> deterministic, graph-capturable.
__device__ unsigned long long g_partial[BATCH * SPLIT];

__device__ __forceinline__ unsigned int float_key(float v) {
    unsigned int u = __float_as_uint(v);
    return (u & 0x80000000u) ? ~u : (u | 0x80000000u);
}

__global__ __launch_bounds__(NT, 8)
void argmax_partial_kernel(const float* __restrict__ logits) {
    const int row   = blockIdx.x >> 2;
    const int chunk = blockIdx.x & 3;
    const float4* __restrict__ p =
        reinterpret_cast<const float4*>(logits)
        + (size_t)row * ROW4 + (size_t)chunk * CHUNK4;
    const int idx_base = chunk * CHUNK4 * 4;

    float best = -__int_as_float(0x7f800000);  // -inf
    int bidx = 0;

    // Per-thread indices ascend, so strict '>' keeps lowest index on ties.
    #pragma unroll 4
    for (int i = threadIdx.x; i < CHUNK4; i += NT) {
        const float4 v = p[i];
        const int base = idx_base + i * 4;
        if (v.x > best) { best = v.x; bidx = base;     }
        if (v.y > best) { best = v.y; bidx = base + 1; }
        if (v.z > best) { best = v.z; bidx = base + 2; }
        if (v.w > best) { best = v.w; bidx = base + 3; }
    }

    // Warp reduction: max value, ties -> smaller index.
    const unsigned full = 0xffffffffu;
    #pragma unroll
    for (int off = 16; off; off >>= 1) {
        const float ov = __shfl_down_sync(full, best, off);
        const int   oi = __shfl_down_sync(full, bidx, off);
        if (ov > best || (ov == best && oi < bidx)) { best = ov; bidx = oi; }
    }

    __shared__ float sv[NWARP];
    __shared__ int   si[NWARP];
    const int wid = threadIdx.x >> 5;
    const int lid = threadIdx.x & 31;
    if (lid == 0) { sv[wid] = best; si[wid] = bidx; }
    __syncthreads();

    if (wid == 0) {
        best = (lid < NWARP) ? sv[lid] : -__int_as_float(0x7f800000);
        bidx = (lid < NWARP) ? si[lid] : 0x7fffffff;
        #pragma unroll
        for (int off = NWARP / 2; off; off >>= 1) {
            const float ov = __shfl_down_sync(full, best, off);
            const int   oi = __shfl_down_sync(full, bidx, off);
            if (ov > best || (ov == best && oi < bidx)) { best = ov; bidx = oi; }
        }
        if (lid == 0) {
            unsigned long long packed =
                ((unsigned long long)float_key(best) << 32) |
                (unsigned int)(~bidx);
            g_partial[blockIdx.x] = packed;
        }
    }
}

__global__ void argmax_finalize_kernel(float* __restrict__ out) {
    const int row = threadIdx.x;  // 256 threads, 1 CTA
    unsigned long long best = 0ull;
    #pragma unroll
    for (int c = 0; c < SPLIT; c++) {
        const unsigned long long v = g_partial[row * SPLIT + c];
        if (v > best) best = v;   // key desc, then ~idx desc == idx asc
    }
    const int idx = (int)(~(unsigned int)best);
    out[row] = (float)idx;
}

extern "C" void kernel_launch(void* const* d_in, const int* in_sizes, int n_in,
                              void* d_out, int out_size) {
    const float* logits = (const float*)d_in[0];
    float* out = (float*)d_out;
    argmax_partial_kernel<<<BATCH * SPLIT, NT>>>(logits);
    argmax_finalize_kernel<<<1, BATCH>>>(out);
}